// round 2
// baseline (speedup 1.0000x reference)
#include <cuda_runtime.h>
#include <cfloat>
#include <math.h>

#define BSZ 8
#define P1  8192
#define P2  2048
#define KNB 32
#define NQ  16384
#define NTOT 524288ull

typedef unsigned long long ull;

__device__ int    g_nn[NQ*KNB];
__device__ float  g_bufA[128*NTOT];   // y1 (64ch), later y3 (128ch)
__device__ float  g_bufB[64*NTOT];    // y2
__device__ double g_sum[128];
__device__ double g_sqsum[128];
__device__ float  g_scale[3][128];
__device__ float  g_shift[3][128];

static __device__ __forceinline__ ull pk2(float x, float y) {
    ull r; asm("mov.b64 %0,{%1,%2};" : "=l"(r) : "f"(x), "f"(y)); return r;
}
static __device__ __forceinline__ void upk2(ull v, float &x, float &y) {
    asm("mov.b64 {%0,%1},%2;" : "=f"(x), "=f"(y) : "l"(v));
}
static __device__ __forceinline__ void fma2(ull &acc, ull a, ull w) {
    asm("fma.rn.f32x2 %0,%1,%2,%0;" : "+l"(acc) : "l"(a), "l"(w));
}

// -------- KNN: warp per query, lane-sorted distributed top-32 --------
__global__ void knn_kernel(const float* __restrict__ xyz,
                           const int*   __restrict__ sidx,
                           float*       __restrict__ out_xyz) {
    extern __shared__ float4 pts[];                 // 8192*16B = 128KB
    const int tid  = threadIdx.x;
    const int warp = tid >> 5, lane = tid & 31;
    const int qbase = blockIdx.x * 16;
    const int b = qbase / P2;
    const float* bx = xyz + (size_t)b * P1 * 3;

    for (int j = tid; j < P1; j += 512) {
        float x = bx[3*j], y = bx[3*j+1], z = bx[3*j+2];
        float r2 = __fadd_rn(__fadd_rn(__fmul_rn(x,x), __fmul_rn(y,y)), __fmul_rn(z,z));
        pts[j] = make_float4(x, y, z, r2);
    }
    __syncthreads();

    const int q  = qbase + warp;
    const int si = sidx[q];
    const float qx = bx[3*si], qy = bx[3*si+1], qz = bx[3*si+2];
    const float rA = __fadd_rn(__fadd_rn(__fmul_rn(qx,qx), __fmul_rn(qy,qy)), __fmul_rn(qz,qz));
    if (lane < 3) out_xyz[(size_t)q*3 + lane] = (lane == 0) ? qx : (lane == 1 ? qy : qz);

    float best_d = FLT_MAX; int best_i = 0;   // sorted ascending across lanes
    float thr = FLT_MAX;

    for (int j0 = 0; j0 < P1; j0 += 32) {
        float4 pt = pts[j0 + lane];
        float dot = __fmaf_rn(qz, pt.z, __fmaf_rn(qy, pt.y, __fmul_rn(qx, pt.x)));
        float d   = __fadd_rn(__fsub_rn(rA, __fmul_rn(2.f, dot)), pt.w);
        unsigned m = __ballot_sync(0xffffffffu, d < thr);
        while (m) {
            int src = __ffs(m) - 1; m &= m - 1;
            float dc = __shfl_sync(0xffffffffu, d, src);
            unsigned bal = __ballot_sync(0xffffffffu, dc < best_d);
            if (bal) {
                int pos  = __ffs(bal) - 1;
                float ud = __shfl_up_sync(0xffffffffu, best_d, 1);
                int   ui = __shfl_up_sync(0xffffffffu, best_i, 1);
                if (lane > pos)       { best_d = ud; best_i = ui; }
                else if (lane == pos) { best_d = dc; best_i = j0 + src; }
                thr = __shfl_sync(0xffffffffu, best_d, 31);
            }
        }
    }
    g_nn[(size_t)q*KNB + lane] = best_i;
}

// -------- conv (+prev BN affine+relu or gather) + BN stat accumulation --------
// activations channel-major [C][NTOT]; block tile 256 samples x 64 outputs
template<int CIN, int MODE>   // MODE0: gather inputs; MODE1: read prev buf + affine + relu
__global__ void layer_kernel(const float* __restrict__ feat,
                             const float* __restrict__ xyz,
                             const float* __restrict__ qxyz,
                             const float* __restrict__ W,
                             const float* __restrict__ Bias,
                             int prev, int in_sel, int out_sel)
{
    extern __shared__ float smem[];
    float* a_sm = smem;                          // [CIN][256]
    ull*   w_sm = (ull*)(smem + CIN*256);        // [CIN][64] duplicated f32x2

    const int tid    = threadIdx.x;
    const int o_base = blockIdx.y * 64;
    const size_t s0  = (size_t)blockIdx.x * 256;

    for (int i = tid; i < CIN*64; i += 256) {
        int o = i & 63, c = i >> 6;
        float w = W[(size_t)(o_base + o)*CIN + c];
        w_sm[i] = pk2(w, w);
    }

    if (MODE == 0) {
        int n  = (int)s0 + tid;
        int b  = n >> 16;                        // P2*KNB = 65536 per batch
        int qg = n >> 5;
        int nn = g_nn[n];
        const float4* frow = (const float4*)(feat + (size_t)(b*P1 + nn)*64);
        #pragma unroll
        for (int i = 0; i < 16; i++) {
            float4 f = frow[i];
            a_sm[(4*i+0)*256 + tid] = f.x;
            a_sm[(4*i+1)*256 + tid] = f.y;
            a_sm[(4*i+2)*256 + tid] = f.z;
            a_sm[(4*i+3)*256 + tid] = f.w;
        }
        const float* nx = xyz  + (size_t)(b*P1 + nn)*3;
        const float* qp = qxyz + (size_t)qg*3;
        a_sm[64*256 + tid] = __fsub_rn(nx[0], qp[0]);
        a_sm[65*256 + tid] = __fsub_rn(nx[1], qp[1]);
        a_sm[66*256 + tid] = __fsub_rn(nx[2], qp[2]);
    } else {
        const float* in = (in_sel == 0) ? g_bufA : g_bufB;
        const float* sc = g_scale[prev];
        const float* sh = g_shift[prev];
        for (int c = 0; c < CIN; c++) {
            float v = in[(size_t)c*NTOT + s0 + tid];
            a_sm[c*256 + tid] = fmaxf(__fmaf_rn(sc[c], v, sh[c]), 0.f);
        }
    }
    __syncthreads();

    const int og = tid >> 5, lane = tid & 31;
    ull acc[4][8];
    #pragma unroll
    for (int oo = 0; oo < 8; oo++) {
        float bv = Bias[o_base + og*8 + oo];
        ull b2 = pk2(bv, bv);
        #pragma unroll
        for (int j = 0; j < 4; j++) acc[j][oo] = b2;
    }

    for (int c = 0; c < CIN; c++) {
        const ull* ap = (const ull*)(a_sm + c*256) + lane;
        ull a0 = ap[0], a1 = ap[32], a2 = ap[64], a3 = ap[96];
        const ull* wr = w_sm + c*64 + og*8;
        #pragma unroll
        for (int oo = 0; oo < 8; oo++) {
            ull w2 = wr[oo];
            fma2(acc[0][oo], a0, w2);
            fma2(acc[1][oo], a1, w2);
            fma2(acc[2][oo], a2, w2);
            fma2(acc[3][oo], a3, w2);
        }
    }

    float* y_out = (out_sel == 0) ? g_bufA : g_bufB;
    #pragma unroll
    for (int oo = 0; oo < 8; oo++) {
        int o = o_base + og*8 + oo;
        float* yp = y_out + (size_t)o*NTOT + s0 + 2*lane;
        float s = 0.f, qq = 0.f;
        #pragma unroll
        for (int j = 0; j < 4; j++) {
            float lo, hi; upk2(acc[j][oo], lo, hi);
            *(float2*)(yp + 64*j) = make_float2(lo, hi);
            s  += lo + hi;
            qq += lo*lo + hi*hi;
        }
        #pragma unroll
        for (int off = 16; off; off >>= 1) {
            s  += __shfl_xor_sync(0xffffffffu, s,  off);
            qq += __shfl_xor_sync(0xffffffffu, qq, off);
        }
        if (lane == 0) {
            atomicAdd(&g_sum[o],   (double)s);
            atomicAdd(&g_sqsum[o], (double)qq);
        }
    }
}

// -------- BN finalize: stats -> affine; re-zero accumulators (graph-replay safe) --------
__global__ void finalize_kernel(const float* __restrict__ gamma,
                                const float* __restrict__ beta,
                                int layer) {
    int o = threadIdx.x;
    double mean = g_sum[o]   * (1.0 / (double)NTOT);
    double var  = g_sqsum[o] * (1.0 / (double)NTOT) - mean*mean;
    float sc = gamma[o] * (float)(1.0 / sqrt(var + 1e-5));
    g_scale[layer][o] = sc;
    g_shift[layer][o] = __fmaf_rn(-(float)mean, sc, beta[o]);
    g_sum[o] = 0.0; g_sqsum[o] = 0.0;
}

// -------- BN3 affine + relu + maxpool over K=32 --------
__global__ void pool_kernel(float* __restrict__ out) {
    int idx = blockIdx.x * 256 + threadIdx.x;    // NQ*128
    int q = idx & (NQ - 1);
    int o = idx >> 14;
    const float4* p = (const float4*)(g_bufA + (size_t)o*NTOT + (size_t)q*KNB);
    float sc = g_scale[2][o], sh = g_shift[2][o];
    float m = 0.f;                                // relu(x) >= 0, so 0 == max of relu when all neg
    #pragma unroll
    for (int i = 0; i < 8; i++) {
        float4 v = p[i];
        m = fmaxf(m, fmaxf(fmaxf(__fmaf_rn(sc,v.x,sh), __fmaf_rn(sc,v.y,sh)),
                           fmaxf(__fmaf_rn(sc,v.z,sh), __fmaf_rn(sc,v.w,sh))));
    }
    out[(size_t)q*128 + o] = m;
}

extern "C" void kernel_launch(void* const* d_in, const int* in_sizes, int n_in,
                              void* d_out, int out_size) {
    const float* xyz  = (const float*)d_in[0];
    const float* feat = (const float*)d_in[1];
    const int*   sidx = (const int*)d_in[2];
    const float *w1=(const float*)d_in[3],  *b1=(const float*)d_in[4],
                *g1=(const float*)d_in[5],  *t1=(const float*)d_in[6];
    const float *w2=(const float*)d_in[7],  *b2=(const float*)d_in[8],
                *g2=(const float*)d_in[9],  *t2=(const float*)d_in[10];
    const float *w3=(const float*)d_in[11], *b3=(const float*)d_in[12],
                *g3=(const float*)d_in[13], *t3=(const float*)d_in[14];
    float* out      = (float*)d_out;
    float* new_xyz  = out;                 // [8,2048,3]
    float* new_feat = out + NQ*3;          // [8,2048,128]

    const int S1 = 67*256*4 + 67*64*8;     // 102912
    const int S2 = 64*256*4 + 64*64*8;     // 98304
    cudaFuncSetAttribute(knn_kernel, cudaFuncAttributeMaxDynamicSharedMemorySize, 131072);
    cudaFuncSetAttribute(layer_kernel<67,0>, cudaFuncAttributeMaxDynamicSharedMemorySize, S1);
    cudaFuncSetAttribute(layer_kernel<64,1>, cudaFuncAttributeMaxDynamicSharedMemorySize, S2);

    knn_kernel<<<NQ/16, 512, 131072>>>(xyz, sidx, new_xyz);
    layer_kernel<67,0><<<dim3(NTOT/256,1), 256, S1>>>(feat, xyz, new_xyz, w1, b1, 0, 0, 0);
    finalize_kernel<<<1,64>>>(g1, t1, 0);
    layer_kernel<64,1><<<dim3(NTOT/256,1), 256, S2>>>(nullptr, nullptr, nullptr, w2, b2, 0, 0, 1);
    finalize_kernel<<<1,64>>>(g2, t2, 1);
    layer_kernel<64,1><<<dim3(NTOT/256,2), 256, S2>>>(nullptr, nullptr, nullptr, w3, b3, 1, 1, 0);
    finalize_kernel<<<1,128>>>(g3, t3, 2);
    pool_kernel<<<(NQ*128)/256, 256>>>(new_feat);
}

// round 3
// speedup vs baseline: 1.0230x; 1.0230x over previous
#include <cuda_runtime.h>
#include <cfloat>
#include <math.h>

#define BSZ 8
#define P1  8192
#define P2  2048
#define KNB 32
#define NQ  16384
#define NTOT 524288ull
#define SAMP 512

typedef unsigned long long ull;

__device__ int    g_nn[NQ*KNB];
__device__ float  g_bufA[128*NTOT];   // y1 (64ch), later y3 (128ch)
__device__ float  g_bufB[64*NTOT];    // y2
__device__ double g_sum[128];
__device__ double g_sqsum[128];
__device__ float  g_scale[3][128];
__device__ float  g_shift[3][128];

static __device__ __forceinline__ ull pk2(float x, float y) {
    ull r; asm("mov.b64 %0,{%1,%2};" : "=l"(r) : "f"(x), "f"(y)); return r;
}
static __device__ __forceinline__ void upk2(ull v, float &x, float &y) {
    asm("mov.b64 {%0,%1},%2;" : "=f"(x), "=f"(y) : "l"(v));
}
static __device__ __forceinline__ void fma2(ull &acc, ull a, ull w) {
    asm("fma.rn.f32x2 %0,%1,%2,%0;" : "+l"(acc) : "l"(a), "l"(w));
}

// -------- KNN: warp per query, lane-sorted distributed top-32 --------
__global__ __launch_bounds__(1024) void knn_kernel(const float* __restrict__ xyz,
                           const int*   __restrict__ sidx,
                           float*       __restrict__ out_xyz) {
    extern __shared__ float4 pts[];                 // 8192*16B = 128KB
    const int tid  = threadIdx.x;
    const int warp = tid >> 5, lane = tid & 31;
    const int qbase = blockIdx.x * 32;
    const int b = qbase / P2;
    const float* bx = xyz + (size_t)b * P1 * 3;

    for (int j = tid; j < P1; j += 1024) {
        float x = bx[3*j], y = bx[3*j+1], z = bx[3*j+2];
        float r2 = __fadd_rn(__fadd_rn(__fmul_rn(x,x), __fmul_rn(y,y)), __fmul_rn(z,z));
        pts[j] = make_float4(x, y, z, r2);
    }
    __syncthreads();

    const int q  = qbase + warp;
    const int si = sidx[q];
    const float qx = bx[3*si], qy = bx[3*si+1], qz = bx[3*si+2];
    const float rA = __fadd_rn(__fadd_rn(__fmul_rn(qx,qx), __fmul_rn(qy,qy)), __fmul_rn(qz,qz));
    if (lane < 3) out_xyz[(size_t)q*3 + lane] = (lane == 0) ? qx : (lane == 1 ? qy : qz);

    float best_d = FLT_MAX; int best_i = 0;   // sorted ascending across lanes
    float thr = FLT_MAX;

    for (int j0 = 0; j0 < P1; j0 += 32) {
        float4 pt = pts[j0 + lane];
        float dot = __fmaf_rn(qz, pt.z, __fmaf_rn(qy, pt.y, __fmul_rn(qx, pt.x)));
        float d   = __fadd_rn(__fsub_rn(rA, __fmul_rn(2.f, dot)), pt.w);
        unsigned m = __ballot_sync(0xffffffffu, d < thr);
        while (m) {
            int src = __ffs(m) - 1; m &= m - 1;
            float dc = __shfl_sync(0xffffffffu, d, src);
            unsigned bal = __ballot_sync(0xffffffffu, dc < best_d);
            if (bal) {
                int pos  = __ffs(bal) - 1;
                float ud = __shfl_up_sync(0xffffffffu, best_d, 1);
                int   ui = __shfl_up_sync(0xffffffffu, best_i, 1);
                if (lane > pos)       { best_d = ud; best_i = ui; }
                else if (lane == pos) { best_d = dc; best_i = j0 + src; }
            }
        }
        thr = __shfl_sync(0xffffffffu, best_d, 31);
    }
    g_nn[(size_t)q*KNB + lane] = best_i;
}

// -------- conv (+prev BN affine+relu or gather) + BN stat accumulation --------
// activations channel-major [C][NTOT]; block tile 512 samples x 64 outputs
// per lane: 8 sample-pairs x 8 outputs, packed f32x2 FMAs
template<int CIN, int MODE>   // MODE0: gather inputs; MODE1: read prev buf + affine + relu
__global__ __launch_bounds__(256, 1) void layer_kernel(
                             const float* __restrict__ feat,
                             const float* __restrict__ xyz,
                             const float* __restrict__ qxyz,
                             const float* __restrict__ W,
                             const float* __restrict__ Bias,
                             int prev, int in_sel, int out_sel)
{
    extern __shared__ float smem[];
    float* a_sm = smem;                          // [CIN][512]
    ull*   w_sm = (ull*)(smem + CIN*SAMP);       // [CIN][64] duplicated f32x2

    const int tid    = threadIdx.x;
    const int o_base = blockIdx.y * 64;
    const size_t s0  = (size_t)blockIdx.x * SAMP;

    for (int i = tid; i < CIN*64; i += 256) {
        int o = i & 63, c = i >> 6;
        float w = W[(size_t)(o_base + o)*CIN + c];
        w_sm[i] = pk2(w, w);
    }

    if (MODE == 0) {
        #pragma unroll
        for (int r = 0; r < 2; r++) {
            int s  = r*256 + tid;
            int n  = (int)s0 + s;
            int b  = n >> 16;                        // P2*KNB = 65536 per batch
            int qg = n >> 5;
            int nn = g_nn[n];
            const float4* frow = (const float4*)(feat + (size_t)(b*P1 + nn)*64);
            #pragma unroll
            for (int i = 0; i < 16; i++) {
                float4 f = frow[i];
                a_sm[(4*i+0)*SAMP + s] = f.x;
                a_sm[(4*i+1)*SAMP + s] = f.y;
                a_sm[(4*i+2)*SAMP + s] = f.z;
                a_sm[(4*i+3)*SAMP + s] = f.w;
            }
            const float* nx = xyz  + (size_t)(b*P1 + nn)*3;
            const float* qp = qxyz + (size_t)qg*3;
            a_sm[64*SAMP + s] = __fsub_rn(nx[0], qp[0]);
            a_sm[65*SAMP + s] = __fsub_rn(nx[1], qp[1]);
            a_sm[66*SAMP + s] = __fsub_rn(nx[2], qp[2]);
        }
    } else {
        const float* in = (in_sel == 0) ? g_bufA : g_bufB;
        const float* sc = g_scale[prev];
        const float* sh = g_shift[prev];
        for (int c = 0; c < CIN; c++) {
            float2 v = *(const float2*)(in + (size_t)c*NTOT + s0 + 2*tid);
            float s_ = sc[c], h_ = sh[c];
            a_sm[c*SAMP + 2*tid]   = fmaxf(__fmaf_rn(s_, v.x, h_), 0.f);
            a_sm[c*SAMP + 2*tid+1] = fmaxf(__fmaf_rn(s_, v.y, h_), 0.f);
        }
    }
    __syncthreads();

    const int og = tid >> 5, lane = tid & 31;
    ull acc[8][8];
    #pragma unroll
    for (int oo = 0; oo < 8; oo++) {
        float bv = Bias[o_base + og*8 + oo];
        ull b2 = pk2(bv, bv);
        #pragma unroll
        for (int j = 0; j < 8; j++) acc[j][oo] = b2;
    }

    #pragma unroll 2
    for (int c = 0; c < CIN; c++) {
        const ull* ap = (const ull*)(a_sm + c*SAMP) + lane;
        ull a[8];
        #pragma unroll
        for (int j = 0; j < 8; j++) a[j] = ap[32*j];
        const ull* wr = w_sm + c*64 + og*8;
        #pragma unroll
        for (int oo = 0; oo < 8; oo++) {
            ull w2 = wr[oo];
            #pragma unroll
            for (int j = 0; j < 8; j++) fma2(acc[j][oo], a[j], w2);
        }
    }

    float* y_out = (out_sel == 0) ? g_bufA : g_bufB;
    #pragma unroll
    for (int oo = 0; oo < 8; oo++) {
        int o = o_base + og*8 + oo;
        float* yp = y_out + (size_t)o*NTOT + s0 + 2*lane;
        float s = 0.f, qq = 0.f;
        #pragma unroll
        for (int j = 0; j < 8; j++) {
            float lo, hi; upk2(acc[j][oo], lo, hi);
            *(float2*)(yp + 64*j) = make_float2(lo, hi);
            s  += lo + hi;
            qq += lo*lo + hi*hi;
        }
        #pragma unroll
        for (int off = 16; off; off >>= 1) {
            s  += __shfl_xor_sync(0xffffffffu, s,  off);
            qq += __shfl_xor_sync(0xffffffffu, qq, off);
        }
        if (lane == 0) {
            atomicAdd(&g_sum[o],   (double)s);
            atomicAdd(&g_sqsum[o], (double)qq);
        }
    }
}

// -------- BN finalize: stats -> affine; re-zero accumulators (graph-replay safe) --------
__global__ void finalize_kernel(const float* __restrict__ gamma,
                                const float* __restrict__ beta,
                                int layer) {
    int o = threadIdx.x;
    double mean = g_sum[o]   * (1.0 / (double)NTOT);
    double var  = g_sqsum[o] * (1.0 / (double)NTOT) - mean*mean;
    float sc = gamma[o] * (float)(1.0 / sqrt(var + 1e-5));
    g_scale[layer][o] = sc;
    g_shift[layer][o] = __fmaf_rn(-(float)mean, sc, beta[o]);
    g_sum[o] = 0.0; g_sqsum[o] = 0.0;
}

// -------- BN3 affine + relu + maxpool over K=32 --------
__global__ void pool_kernel(float* __restrict__ out) {
    int idx = blockIdx.x * 256 + threadIdx.x;    // NQ*128
    int q = idx & (NQ - 1);
    int o = idx >> 14;
    const float4* p = (const float4*)(g_bufA + (size_t)o*NTOT + (size_t)q*KNB);
    float sc = g_scale[2][o], sh = g_shift[2][o];
    float m = 0.f;                                // relu >= 0
    #pragma unroll
    for (int i = 0; i < 8; i++) {
        float4 v = p[i];
        m = fmaxf(m, fmaxf(fmaxf(__fmaf_rn(sc,v.x,sh), __fmaf_rn(sc,v.y,sh)),
                           fmaxf(__fmaf_rn(sc,v.z,sh), __fmaf_rn(sc,v.w,sh))));
    }
    out[(size_t)q*128 + o] = m;
}

extern "C" void kernel_launch(void* const* d_in, const int* in_sizes, int n_in,
                              void* d_out, int out_size) {
    const float* xyz  = (const float*)d_in[0];
    const float* feat = (const float*)d_in[1];
    const int*   sidx = (const int*)d_in[2];
    const float *w1=(const float*)d_in[3],  *b1=(const float*)d_in[4],
                *g1=(const float*)d_in[5],  *t1=(const float*)d_in[6];
    const float *w2=(const float*)d_in[7],  *b2=(const float*)d_in[8],
                *g2=(const float*)d_in[9],  *t2=(const float*)d_in[10];
    const float *w3=(const float*)d_in[11], *b3=(const float*)d_in[12],
                *g3=(const float*)d_in[13], *t3=(const float*)d_in[14];
    float* out      = (float*)d_out;
    float* new_xyz  = out;                 // [8,2048,3]
    float* new_feat = out + NQ*3;          // [8,2048,128]

    const int S1 = 67*SAMP*4 + 67*64*8;    // 171520
    const int S2 = 64*SAMP*4 + 64*64*8;    // 163840
    cudaFuncSetAttribute(knn_kernel, cudaFuncAttributeMaxDynamicSharedMemorySize, 131072);
    cudaFuncSetAttribute(layer_kernel<67,0>, cudaFuncAttributeMaxDynamicSharedMemorySize, S1);
    cudaFuncSetAttribute(layer_kernel<64,1>, cudaFuncAttributeMaxDynamicSharedMemorySize, S2);

    knn_kernel<<<NQ/32, 1024, 131072>>>(xyz, sidx, new_xyz);
    layer_kernel<67,0><<<dim3(NTOT/SAMP,1), 256, S1>>>(feat, xyz, new_xyz, w1, b1, 0, 0, 0);
    finalize_kernel<<<1,64>>>(g1, t1, 0);
    layer_kernel<64,1><<<dim3(NTOT/SAMP,1), 256, S2>>>(nullptr, nullptr, nullptr, w2, b2, 0, 0, 1);
    finalize_kernel<<<1,64>>>(g2, t2, 1);
    layer_kernel<64,1><<<dim3(NTOT/SAMP,2), 256, S2>>>(nullptr, nullptr, nullptr, w3, b3, 1, 1, 0);
    finalize_kernel<<<1,128>>>(g3, t3, 2);
    pool_kernel<<<(NQ*128)/256, 256>>>(new_feat);
}

// round 4
// speedup vs baseline: 1.1079x; 1.0830x over previous
#include <cuda_runtime.h>
#include <cfloat>
#include <math.h>

#define BSZ 8
#define P1  8192
#define P2  2048
#define KNB 32
#define NQ  16384
#define NTOT 524288ull
#define SAMP 256

typedef unsigned long long ull;

__device__ int    g_nn[NQ*KNB];
__device__ float  g_bufA[64*NTOT];    // y1
__device__ float  g_bufB[64*NTOT];    // y2
__device__ float  g_mx[NQ*128];       // raw y3 per-query max  [q][o]
__device__ float  g_mn[NQ*128];       // raw y3 per-query min
__device__ double g_sum[128];
__device__ double g_sqsum[128];
__device__ float  g_scale[3][128];
__device__ float  g_shift[3][128];

static __device__ __forceinline__ ull pk2(float x, float y) {
    ull r; asm("mov.b64 %0,{%1,%2};" : "=l"(r) : "f"(x), "f"(y)); return r;
}
static __device__ __forceinline__ void upk2(ull v, float &x, float &y) {
    asm("mov.b64 {%0,%1},%2;" : "=f"(x), "=f"(y) : "l"(v));
}
static __device__ __forceinline__ void fma2(ull &acc, ull a, ull w) {
    asm("fma.rn.f32x2 %0,%1,%2,%0;" : "+l"(acc) : "l"(a), "l"(w));
}

// -------- KNN: warp per query, lane-sorted distributed top-32 --------
__global__ __launch_bounds__(1024) void knn_kernel(const float* __restrict__ xyz,
                           const int*   __restrict__ sidx,
                           float*       __restrict__ out_xyz) {
    extern __shared__ float4 pts[];                 // 128KB
    const int tid  = threadIdx.x;
    const int warp = tid >> 5, lane = tid & 31;
    const int qbase = blockIdx.x * 32;
    const int b = qbase / P2;
    const float* bx = xyz + (size_t)b * P1 * 3;

    for (int j = tid; j < P1; j += 1024) {
        float x = bx[3*j], y = bx[3*j+1], z = bx[3*j+2];
        float r2 = __fadd_rn(__fadd_rn(__fmul_rn(x,x), __fmul_rn(y,y)), __fmul_rn(z,z));
        pts[j] = make_float4(x, y, z, r2);
    }
    __syncthreads();

    const int q  = qbase + warp;
    const int si = sidx[q];
    const float qx = bx[3*si], qy = bx[3*si+1], qz = bx[3*si+2];
    const float rA = __fadd_rn(__fadd_rn(__fmul_rn(qx,qx), __fmul_rn(qy,qy)), __fmul_rn(qz,qz));
    if (lane < 3) out_xyz[(size_t)q*3 + lane] = (lane == 0) ? qx : (lane == 1 ? qy : qz);

    float best_d = FLT_MAX; int best_i = 0;   // ascending across lanes
    float thr = FLT_MAX;

    for (int j0 = 0; j0 < P1; j0 += 32) {
        float4 pt = pts[j0 + lane];
        float dot = __fmaf_rn(qz, pt.z, __fmaf_rn(qy, pt.y, __fmul_rn(qx, pt.x)));
        float d   = __fadd_rn(__fsub_rn(rA, __fmul_rn(2.f, dot)), pt.w);
        unsigned m = __ballot_sync(0xffffffffu, d < thr);
        while (m) {
            int src = __ffs(m) - 1; m &= m - 1;
            float dc = __shfl_sync(0xffffffffu, d, src);
            unsigned bal = __ballot_sync(0xffffffffu, dc < best_d);
            if (bal) {
                int pos  = __ffs(bal) - 1;
                float ud = __shfl_up_sync(0xffffffffu, best_d, 1);
                int   ui = __shfl_up_sync(0xffffffffu, best_i, 1);
                if (lane > pos)       { best_d = ud; best_i = ui; }
                else if (lane == pos) { best_d = dc; best_i = j0 + src; }
            }
        }
        thr = __shfl_sync(0xffffffffu, best_d, 31);
    }
    g_nn[(size_t)q*KNB + lane] = best_i;
}

// -------- conv (+prev BN affine+relu or gather) + BN stats (+ fused pool) --------
// block tile: 256 samples x 64 outputs, 256 threads, 2 CTAs/SM.
// lane accs: k=2h+p -> samples 128h + 4*lane + 2p + {0,1}; 8 outputs per warp.
template<int CIN, int MODE, int POOL>
__global__ __launch_bounds__(256, 2) void layer_kernel(
                             const float* __restrict__ feat,
                             const float* __restrict__ xyz,
                             const float* __restrict__ qxyz,
                             const float* __restrict__ W,
                             const float* __restrict__ Bias,
                             const float* __restrict__ in,
                             float*       __restrict__ y_out,
                             int prev)
{
    extern __shared__ float smem[];
    float* a_sm = smem;                          // [CIN][256]
    ull*   w_sm = (ull*)(smem + CIN*SAMP);       // [CIN][64] duplicated f32x2

    const int tid    = threadIdx.x;
    const int o_base = blockIdx.y * 64;
    const size_t s0  = (size_t)blockIdx.x * SAMP;

    for (int i = tid; i < CIN*64; i += 256) {
        int o = i & 63, c = i >> 6;
        float w = W[(size_t)(o_base + o)*CIN + c];
        w_sm[i] = pk2(w, w);
    }

    if (MODE == 0) {
        int n  = (int)s0 + tid;
        int b  = n >> 16;                        // P2*KNB = 65536 per batch
        int qg = n >> 5;
        int nn = g_nn[n];
        const float4* frow = (const float4*)(feat + (size_t)(b*P1 + nn)*64);
        #pragma unroll
        for (int i = 0; i < 16; i++) {
            float4 f = frow[i];
            a_sm[(4*i+0)*SAMP + tid] = f.x;
            a_sm[(4*i+1)*SAMP + tid] = f.y;
            a_sm[(4*i+2)*SAMP + tid] = f.z;
            a_sm[(4*i+3)*SAMP + tid] = f.w;
        }
        const float* nx = xyz  + (size_t)(b*P1 + nn)*3;
        const float* qp = qxyz + (size_t)qg*3;
        a_sm[64*SAMP + tid] = __fsub_rn(nx[0], qp[0]);
        a_sm[65*SAMP + tid] = __fsub_rn(nx[1], qp[1]);
        a_sm[66*SAMP + tid] = __fsub_rn(nx[2], qp[2]);
    } else {
        const float* sc = g_scale[prev];
        const float* sh = g_shift[prev];
        for (int i = tid; i < CIN*64; i += 256) {
            int c = i >> 6, s4 = (i & 63) * 4;
            float4 v = *(const float4*)(in + (size_t)c*NTOT + s0 + s4);
            float s_ = sc[c], h_ = sh[c];
            v.x = fmaxf(__fmaf_rn(s_, v.x, h_), 0.f);
            v.y = fmaxf(__fmaf_rn(s_, v.y, h_), 0.f);
            v.z = fmaxf(__fmaf_rn(s_, v.z, h_), 0.f);
            v.w = fmaxf(__fmaf_rn(s_, v.w, h_), 0.f);
            *(float4*)(a_sm + c*SAMP + s4) = v;
        }
    }
    __syncthreads();

    const int og = tid >> 5, lane = tid & 31;
    ull acc[4][8];
    #pragma unroll
    for (int oo = 0; oo < 8; oo++) {
        float bv = Bias[o_base + og*8 + oo];
        ull b2 = pk2(bv, bv);
        #pragma unroll
        for (int k = 0; k < 4; k++) acc[k][oo] = b2;
    }

    #pragma unroll 2
    for (int c = 0; c < CIN; c++) {
        const float* ar = a_sm + c*SAMP + 4*lane;
        ulonglong2 a01 = *(const ulonglong2*)ar;
        ulonglong2 a23 = *(const ulonglong2*)(ar + 128);
        const ulonglong2* wr = (const ulonglong2*)(w_sm + c*64 + og*8);
        #pragma unroll
        for (int ow = 0; ow < 4; ow++) {
            ulonglong2 w2 = wr[ow];
            fma2(acc[0][2*ow],   a01.x, w2.x);
            fma2(acc[1][2*ow],   a01.y, w2.x);
            fma2(acc[2][2*ow],   a23.x, w2.x);
            fma2(acc[3][2*ow],   a23.y, w2.x);
            fma2(acc[0][2*ow+1], a01.x, w2.y);
            fma2(acc[1][2*ow+1], a01.y, w2.y);
            fma2(acc[2][2*ow+1], a23.x, w2.y);
            fma2(acc[3][2*ow+1], a23.y, w2.y);
        }
    }

    #pragma unroll
    for (int oo = 0; oo < 8; oo++) {
        int o = o_base + og*8 + oo;
        float s = 0.f, qq = 0.f;
        float lo0, hi0, lo1, hi1, lo2, hi2, lo3, hi3;
        upk2(acc[0][oo], lo0, hi0); upk2(acc[1][oo], lo1, hi1);
        upk2(acc[2][oo], lo2, hi2); upk2(acc[3][oo], lo3, hi3);
        s  = (lo0+hi0)+(lo1+hi1)+(lo2+hi2)+(lo3+hi3);
        qq = (lo0*lo0+hi0*hi0)+(lo1*lo1+hi1*hi1)+(lo2*lo2+hi2*hi2)+(lo3*lo3+hi3*hi3);
        #pragma unroll
        for (int off = 16; off; off >>= 1) {
            s  += __shfl_xor_sync(0xffffffffu, s,  off);
            qq += __shfl_xor_sync(0xffffffffu, qq, off);
        }
        if (lane == 0) {
            atomicAdd(&g_sum[o],   (double)s);
            atomicAdd(&g_sqsum[o], (double)qq);
        }
        if (POOL) {
            // max/min over each query's 32 samples (qg = 4h + lane/8)
            #pragma unroll
            for (int h = 0; h < 2; h++) {
                float mx = fmaxf(fmaxf(h ? lo2 : lo0, h ? hi2 : hi0),
                                 fmaxf(h ? lo3 : lo1, h ? hi3 : hi1));
                float mn = fminf(fminf(h ? lo2 : lo0, h ? hi2 : hi0),
                                 fminf(h ? lo3 : lo1, h ? hi3 : hi1));
                #pragma unroll
                for (int off = 4; off; off >>= 1) {
                    mx = fmaxf(mx, __shfl_xor_sync(0xffffffffu, mx, off));
                    mn = fminf(mn, __shfl_xor_sync(0xffffffffu, mn, off));
                }
                if ((lane & 7) == 0) {
                    int q = (int)(s0 >> 5) + 4*h + (lane >> 3);
                    g_mx[(size_t)q*128 + o] = mx;
                    g_mn[(size_t)q*128 + o] = mn;
                }
            }
        } else {
            float* yp = y_out + (size_t)o*NTOT + s0 + 4*lane;
            *(float4*)yp         = make_float4(lo0, hi0, lo1, hi1);
            *(float4*)(yp + 128) = make_float4(lo2, hi2, lo3, hi3);
        }
    }
}

// -------- BN finalize --------
__global__ void finalize_kernel(const float* __restrict__ gamma,
                                const float* __restrict__ beta,
                                int layer) {
    int o = threadIdx.x;
    double mean = g_sum[o]   * (1.0 / (double)NTOT);
    double var  = g_sqsum[o] * (1.0 / (double)NTOT) - mean*mean;
    float sc = gamma[o] * (float)(1.0 / sqrt(var + 1e-5));
    g_scale[layer][o] = sc;
    g_shift[layer][o] = __fmaf_rn(-(float)mean, sc, beta[o]);
    g_sum[o] = 0.0; g_sqsum[o] = 0.0;
}

// -------- final: affine+relu on pooled max/min (monotone trick) --------
__global__ void pool_apply_kernel(float* __restrict__ out) {
    int idx = blockIdx.x * 256 + threadIdx.x;   // NQ*128
    int o = idx & 127;
    float sc = g_scale[2][o], sh = g_shift[2][o];
    float vmx = __fmaf_rn(sc, g_mx[idx], sh);
    float vmn = __fmaf_rn(sc, g_mn[idx], sh);
    out[idx] = fmaxf(fmaxf(vmx, vmn), 0.f);
}

extern "C" void kernel_launch(void* const* d_in, const int* in_sizes, int n_in,
                              void* d_out, int out_size) {
    const float* xyz  = (const float*)d_in[0];
    const float* feat = (const float*)d_in[1];
    const int*   sidx = (const int*)d_in[2];
    const float *w1=(const float*)d_in[3],  *b1=(const float*)d_in[4],
                *g1=(const float*)d_in[5],  *t1=(const float*)d_in[6];
    const float *w2=(const float*)d_in[7],  *b2=(const float*)d_in[8],
                *g2=(const float*)d_in[9],  *t2=(const float*)d_in[10];
    const float *w3=(const float*)d_in[11], *b3=(const float*)d_in[12],
                *g3=(const float*)d_in[13], *t3=(const float*)d_in[14];
    float* out      = (float*)d_out;
    float* new_xyz  = out;
    float* new_feat = out + NQ*3;

    float* bufA; cudaGetSymbolAddress((void**)&bufA, g_bufA);
    float* bufB; cudaGetSymbolAddress((void**)&bufB, g_bufB);

    const int S1 = 67*SAMP*4 + 67*64*8;    // 102912
    const int S2 = 64*SAMP*4 + 64*64*8;    // 98304
    cudaFuncSetAttribute(knn_kernel, cudaFuncAttributeMaxDynamicSharedMemorySize, 131072);
    cudaFuncSetAttribute(layer_kernel<67,0,0>, cudaFuncAttributeMaxDynamicSharedMemorySize, S1);
    cudaFuncSetAttribute(layer_kernel<64,1,0>, cudaFuncAttributeMaxDynamicSharedMemorySize, S2);
    cudaFuncSetAttribute(layer_kernel<64,1,1>, cudaFuncAttributeMaxDynamicSharedMemorySize, S2);

    knn_kernel<<<NQ/32, 1024, 131072>>>(xyz, sidx, new_xyz);
    layer_kernel<67,0,0><<<dim3(NTOT/SAMP,1), 256, S1>>>(feat, xyz, new_xyz, w1, b1, nullptr, bufA, 0);
    finalize_kernel<<<1,64>>>(g1, t1, 0);
    layer_kernel<64,1,0><<<dim3(NTOT/SAMP,1), 256, S2>>>(nullptr, nullptr, nullptr, w2, b2, bufA, bufB, 0);
    finalize_kernel<<<1,64>>>(g2, t2, 1);
    layer_kernel<64,1,1><<<dim3(NTOT/SAMP,2), 256, S2>>>(nullptr, nullptr, nullptr, w3, b3, bufB, nullptr, 1);
    finalize_kernel<<<1,128>>>(g3, t3, 2);
    pool_apply_kernel<<<(NQ*128)/256, 256>>>(new_feat);
}